// round 3
// baseline (speedup 1.0000x reference)
#include <cuda_runtime.h>

// Depthwise 3x3 conv (256 ch x 2 filters) fused with butterfly wing-swap add.
//   out[c]  = conv(x[c],  w[2c])   + conv(x[cp], w[2cp+1])
//   out[cp] = conv(x[cp], w[2cp])  + conv(x[c],  w[2c+1]),   cp = c+4 within 8-ch butterfly
// Block = (batch, channel-pair); full 56x56 planes in smem (input read once chip-wide).
// Each thread computes a 7-row x 4-col strip for BOTH outputs via packed fma.rn.f32x2,
// streaming input rows with a rolling 3-row accumulator (early float4 stores).
// Row height 7 + ST=61 makes all compute LDS provably bank-conflict-free.

#define CH 256
#define HW 56
#define PLANE (HW * HW)
#define ST 61
#define SROWS 58
#define NTHREADS 128

typedef unsigned long long ull;

__device__ __forceinline__ ull fma2(ull a, ull b, ull c) {
    ull d; asm("fma.rn.f32x2 %0, %1, %2, %3;" : "=l"(d) : "l"(a), "l"(b), "l"(c)); return d;
}
__device__ __forceinline__ ull pack2(float lo, float hi) {
    ull r; asm("mov.b64 %0, {%1, %2};" : "=l"(r) : "f"(lo), "f"(hi)); return r;
}
__device__ __forceinline__ float2 unpack2(ull v) {
    float2 r; asm("mov.b64 {%0, %1}, %2;" : "=f"(r.x), "=f"(r.y) : "l"(v)); return r;
}

__global__ __launch_bounds__(NTHREADS, 4)
void conv_butterfly_kernel(const float* __restrict__ x,
                           const float* __restrict__ w,
                           float* __restrict__ out)
{
    __shared__ float s0[SROWS * ST];   // plane of channel c   (halo-padded, +1 offset)
    __shared__ float s1[SROWS * ST];   // plane of channel cp

    const int p = blockIdx.x;                 // 0..127 channel pair
    const int n = blockIdx.y;                 // 0..31 batch
    const int c  = ((p >> 2) << 3) + (p & 3);
    const int cp = c + 4;
    const int tid = threadIdx.x;

    const float4* xv0 = (const float4*)(x + ((size_t)n * CH + c)  * PLANE);
    const float4* xv1 = (const float4*)(x + ((size_t)n * CH + cp) * PLANE);

    // ---- load both planes: 56 rows x 14 float4 each. data (h,d) -> smem[(h+1)*ST + d+1]
    for (int i = tid; i < 2 * 784; i += NTHREADS) {
        const int chn = (i >= 784);
        const int ii  = chn ? i - 784 : i;
        const float4 v = chn ? xv1[ii] : xv0[ii];
        const int row = ii / 14;
        const int c4  = ii - row * 14;
        float* s = chn ? s1 : s0;
        const int off = (row + 1) * ST + c4 * 4 + 1;
        s[off + 0] = v.x; s[off + 1] = v.y; s[off + 2] = v.z; s[off + 3] = v.w;
    }
    // ---- zero halo (rows 0 & 57 width 58; cols 0 & 57 of rows 1..56)
    for (int i = tid; i < 2 * 228; i += NTHREADS) {
        const int chn = (i >= 228);
        const int j = chn ? i - 228 : i;
        float* s = chn ? s1 : s0;
        int off;
        if (j < 58)        off = j;
        else if (j < 116)  off = 57 * ST + (j - 58);
        else { const int k = j - 116; off = (1 + (k >> 1)) * ST + (k & 1) * 57; }
        s[off] = 0.f;
    }

    // ---- packed weights: lo half -> out[c], hi half -> out[cp]
    ull wp0[9], wp1[9];
    const float* wa = w + 18 * c;     // [w2c | w2c+1]
    const float* wb = w + 18 * cp;    // [w2cp | w2cp+1]
    #pragma unroll
    for (int k = 0; k < 9; k++) {
        wp0[k] = pack2(__ldg(wa + k),     __ldg(wa + 9 + k));   // for s0 data
        wp1[k] = pack2(__ldg(wb + 9 + k), __ldg(wb + k));       // for s1 data
    }

    __syncthreads();

    // ---- thread -> 7-row x 4-col patch
    const int g    = tid >> 5;          // warp 0..3
    const int lane = tid & 31;
    const int lr   = lane & 3;
    const int lc   = lane >> 2;         // 0..7
    const int rowslot = ((g & 1) << 2) | lr;   // 0..7  (7 rows each)
    const int phase   = g >> 1;
    const int strip   = (phase << 3) + lc;     // 0..15, active < 14
    if (strip >= 14) return;

    const int r0 = rowslot * 7;         // output rows r0..r0+6
    const int c0 = strip << 2;          // output cols c0..c0+3

    float* o0 = out + ((size_t)n * CH + c)  * PLANE;
    float* o1 = out + ((size_t)n * CH + cp) * PLANE;

    ull acc[3][4];                      // rolling accumulators, slot = orow % 3

    #pragma unroll
    for (int k = 0; k < 9; k++) {       // window row k = input row r0-1+k
        const float* qa = s0 + (r0 + k) * ST + c0;   // smem col c0+j = data col c0-1+j
        const float* qb = s1 + (r0 + k) * ST + c0;
        ull va[6], vb[6];
        #pragma unroll
        for (int j = 0; j < 6; j++) { const float v = qa[j]; va[j] = pack2(v, v); }
        #pragma unroll
        for (int j = 0; j < 6; j++) { const float v = qb[j]; vb[j] = pack2(v, v); }

        #pragma unroll
        for (int t = 0; t < 3; t++) {   // kernel row
            const int orow = k - t;     // local output row receiving this input row
            if (orow < 0 || orow > 6) continue;
            ull* A = acc[orow % 3];
            if (t == 0) { A[0] = 0ull; A[1] = 0ull; A[2] = 0ull; A[3] = 0ull; }
            #pragma unroll
            for (int dc = 0; dc < 3; dc++) {
                const ull wA = wp0[t * 3 + dc];
                const ull wB = wp1[t * 3 + dc];
                #pragma unroll
                for (int col = 0; col < 4; col++) {
                    A[col] = fma2(va[col + dc], wA, A[col]);
                    A[col] = fma2(vb[col + dc], wB, A[col]);
                }
            }
        }

        if (k >= 2) {                   // output row k-2 is complete -> store
            const int orow = k - 2;
            ull* A = acc[orow % 3];
            const float2 u0 = unpack2(A[0]), u1 = unpack2(A[1]);
            const float2 u2 = unpack2(A[2]), u3 = unpack2(A[3]);
            float4 lo; lo.x = u0.x; lo.y = u1.x; lo.z = u2.x; lo.w = u3.x;
            float4 hi; hi.x = u0.y; hi.y = u1.y; hi.z = u2.y; hi.w = u3.y;
            *(float4*)(o0 + (r0 + orow) * HW + c0) = lo;
            *(float4*)(o1 + (r0 + orow) * HW + c0) = hi;
        }
    }
}

extern "C" void kernel_launch(void* const* d_in, const int* in_sizes, int n_in,
                              void* d_out, int out_size)
{
    const float* x = (const float*)d_in[0];
    const float* w = (const float*)d_in[1];
    float* out = (float*)d_out;
    (void)in_sizes; (void)n_in; (void)out_size;

    dim3 grid(CH / 2, 32);   // (128 pairs, 32 batch)
    conv_butterfly_kernel<<<grid, NTHREADS>>>(x, w, out);
}

// round 4
// speedup vs baseline: 1.4133x; 1.4133x over previous
#include <cuda_runtime.h>
#include <stdint.h>

// Depthwise 3x3 conv (256 ch x 2 filters) fused with butterfly wing-swap add.
//   out[c]  = conv(x[c],  w[2c])   + conv(x[cp], w[2cp+1])
//   out[cp] = conv(x[cp], w[2cp])  + conv(x[c],  w[2c+1]),  cp = c+4 within 8-ch butterfly
// Persistent blocks (grid=444, ~3/SM), each processes ~9 (batch, pair) tiles with a
// double-buffered cp.async pipeline: prefetch tile k+1 while computing tile k.
// Compute: (a,b)-packed fma.rn.f32x2 — v=(x_c, x_cp), Wc=(w2c, w2cp1), Wp=(w2c1, w2cp),
// out = lo+hi. LDS pattern (stride 61, 4-row x stride-4-col lanes) is conflict-free.

#define CH 256
#define HW 56
#define PLANE (HW * HW)
#define ST 61
#define SROWS 58
#define SPLANE (SROWS * ST)
#define NTHREADS 256
#define GRID 444
#define NTILES 4096   // 32 batch * 128 pairs

typedef unsigned long long ull;

__device__ __forceinline__ ull fma2(ull a, ull b, ull c) {
    ull d; asm("fma.rn.f32x2 %0, %1, %2, %3;" : "=l"(d) : "l"(a), "l"(b), "l"(c)); return d;
}
__device__ __forceinline__ ull pack2(float lo, float hi) {
    ull r; asm("mov.b64 %0, {%1, %2};" : "=l"(r) : "f"(lo), "f"(hi)); return r;
}
__device__ __forceinline__ float2 unpack2(ull v) {
    float2 r; asm("mov.b64 {%0, %1}, %2;" : "=f"(r.x), "=f"(r.y) : "l"(v)); return r;
}
__device__ __forceinline__ void cpasync4(uint32_t dst, const float* src) {
    asm volatile("cp.async.ca.shared.global [%0], [%1], 4;" :: "r"(dst), "l"(src));
}

__global__ __launch_bounds__(NTHREADS, 3)
void conv_butterfly_kernel(const float* __restrict__ x,
                           const float* __restrict__ w,
                           float* __restrict__ out)
{
    extern __shared__ float smbuf[];          // [2 bufs][2 channels][SPLANE]
    const int tid    = threadIdx.x;
    const int warpid = tid >> 5;
    const int lane   = tid & 31;
    const uint32_t smem0 = (uint32_t)__cvta_generic_to_shared(smbuf);

    // ---- zero halos of all 4 planes once (interior loads never touch them)
    if (tid < 228) {
        int j = tid, off;
        if (j < 58)        off = j;
        else if (j < 116)  off = 57 * ST + (j - 58);
        else { int k = j - 116; off = (1 + (k >> 1)) * ST + (k & 1) * 57; }
        smbuf[0 * SPLANE + off] = 0.f; smbuf[1 * SPLANE + off] = 0.f;
        smbuf[2 * SPLANE + off] = 0.f; smbuf[3 * SPLANE + off] = 0.f;
    }

    // prefetch tile t into buffer b: warp handles rows r = warpid + 8k (112 rows = 2ch x 56)
    auto prefetch = [&](int t, int b) {
        const int p = t & 127, n = t >> 7;
        const int c = ((p >> 2) << 3) + (p & 3);
        const float* base = x + ((size_t)n * CH + c) * PLANE;
        #pragma unroll
        for (int k = 0; k < 14; k++) {
            const int r   = warpid + (k << 3);
            const int chB = (r >= HW);
            const int rr  = chB ? r - HW : r;
            const float* src = base + (chB ? 4 * PLANE : 0) + rr * HW + lane;
            const uint32_t dst = smem0 +
                (uint32_t)(((b * 2 + chB) * SPLANE + (rr + 1) * ST + 1 + lane) * 4);
            cpasync4(dst, src);
            if (lane < 24) cpasync4(dst + 128, src + 32);
        }
    };

    const int lr = lane & 3;
    const int lc = lane >> 2;

    int t = blockIdx.x;
    int b = 0;
    prefetch(t, 0);
    asm volatile("cp.async.commit_group;");

    while (t < NTILES) {
        const int tn = t + GRID;
        if (tn < NTILES) prefetch(tn, b ^ 1);
        asm volatile("cp.async.commit_group;");

        // ---- weights for current tile (LDG latency hidden behind cp.async wait)
        const int p = t & 127, n = t >> 7;
        const int c = ((p >> 2) << 3) + (p & 3), cpc = c + 4;
        const float* wa = w + 18 * c;     // [w2c | w2c+1]
        const float* wb = w + 18 * cpc;   // [w2cp | w2cp+1]
        ull Wc[9], Wp[9];
        #pragma unroll
        for (int k = 0; k < 9; k++) {
            Wc[k] = pack2(__ldg(wa + k),     __ldg(wb + 9 + k));  // (w2c,  w2cp1) -> out c
            Wp[k] = pack2(__ldg(wa + 9 + k), __ldg(wb + k));      // (w2c1, w2cp)  -> out cp
        }

        asm volatile("cp.async.wait_group 1;");
        __syncthreads();

        const float* s0 = smbuf + (b * 2 + 0) * SPLANE;
        const float* s1 = smbuf + (b * 2 + 1) * SPLANE;
        float* o0 = out + ((size_t)n * CH + c) * PLANE;
        float* o1 = o0 + 4 * PLANE;

        #pragma unroll
        for (int it0 = 0; it0 < 4; it0++) {
            const int it = warpid + (it0 << 3);
            if (it >= 28) break;                      // warp-uniform
            const int c4 = ((it & 1) << 3) + lc;      // strip, active < 14
            const int r  = ((it >> 1) << 2) + lr;     // output row
            const int c0 = c4 << 2;
            if (c4 < 14) {
                ull a0 = 0, a1 = 0, a2 = 0, a3 = 0;
                ull p0 = 0, p1 = 0, p2 = 0, p3 = 0;
                #pragma unroll
                for (int dr = 0; dr < 3; dr++) {
                    const float* qa = s0 + (r + dr) * ST + c0;
                    const float* qb = s1 + (r + dr) * ST + c0;
                    ull v[6];
                    #pragma unroll
                    for (int j = 0; j < 6; j++) v[j] = pack2(qa[j], qb[j]);
                    const ull wc0 = Wc[dr*3+0], wc1 = Wc[dr*3+1], wc2 = Wc[dr*3+2];
                    const ull wq0 = Wp[dr*3+0], wq1 = Wp[dr*3+1], wq2 = Wp[dr*3+2];
                    a0 = fma2(v[0], wc0, a0); a0 = fma2(v[1], wc1, a0); a0 = fma2(v[2], wc2, a0);
                    a1 = fma2(v[1], wc0, a1); a1 = fma2(v[2], wc1, a1); a1 = fma2(v[3], wc2, a1);
                    a2 = fma2(v[2], wc0, a2); a2 = fma2(v[3], wc1, a2); a2 = fma2(v[4], wc2, a2);
                    a3 = fma2(v[3], wc0, a3); a3 = fma2(v[4], wc1, a3); a3 = fma2(v[5], wc2, a3);
                    p0 = fma2(v[0], wq0, p0); p0 = fma2(v[1], wq1, p0); p0 = fma2(v[2], wq2, p0);
                    p1 = fma2(v[1], wq0, p1); p1 = fma2(v[2], wq1, p1); p1 = fma2(v[3], wq2, p1);
                    p2 = fma2(v[2], wq0, p2); p2 = fma2(v[3], wq1, p2); p2 = fma2(v[4], wq2, p2);
                    p3 = fma2(v[3], wq0, p3); p3 = fma2(v[4], wq1, p3); p3 = fma2(v[5], wq2, p3);
                }
                float2 u;
                float4 lo, hi;
                u = unpack2(a0); lo.x = u.x + u.y;
                u = unpack2(a1); lo.y = u.x + u.y;
                u = unpack2(a2); lo.z = u.x + u.y;
                u = unpack2(a3); lo.w = u.x + u.y;
                u = unpack2(p0); hi.x = u.x + u.y;
                u = unpack2(p1); hi.y = u.x + u.y;
                u = unpack2(p2); hi.z = u.x + u.y;
                u = unpack2(p3); hi.w = u.x + u.y;
                *(float4*)(o0 + r * HW + c0) = lo;
                *(float4*)(o1 + r * HW + c0) = hi;
            }
        }
        __syncthreads();     // protect buffer b before it is refilled next iteration
        t = tn;
        b ^= 1;
    }
}

extern "C" void kernel_launch(void* const* d_in, const int* in_sizes, int n_in,
                              void* d_out, int out_size)
{
    const float* x = (const float*)d_in[0];
    const float* w = (const float*)d_in[1];
    float* out = (float*)d_out;
    (void)in_sizes; (void)n_in; (void)out_size;

    const int smem_bytes = 4 * SPLANE * (int)sizeof(float);   // 56,608 B
    cudaFuncSetAttribute(conv_butterfly_kernel,
                         cudaFuncAttributeMaxDynamicSharedMemorySize, smem_bytes);
    conv_butterfly_kernel<<<GRID, NTHREADS, smem_bytes>>>(x, w, out);
}

// round 5
// speedup vs baseline: 1.6947x; 1.1991x over previous
#include <cuda_runtime.h>
#include <stdint.h>

// Depthwise 3x3 conv (256 ch x 2 filters) fused with butterfly wing-swap add.
//   out[c]  = conv(x[c],  w[2c])   + conv(x[cp], w[2cp+1])
//   out[cp] = conv(x[cp], w[2cp])  + conv(x[c],  w[2c+1]),  cp = c+4 within butterfly
// Persistent blocks, half-plane (28-row) tiles, double-buffered cp.async pipeline.
// Smem layout: channel-interleaved float2 (x_c, x_cp) per cell -> LDS.64 feeds
// fma.rn.f32x2 directly. Packed weights staged in shared per tile.

#define CH 256
#define HW 56
#define PLANE (HW * HW)
#define ST2 61                 // float2 elements per smem row (odd -> conflict-free)
#define TROWS 30               // 28 data rows + 2 halo slots
#define SPLANE2 (TROWS * ST2)  // 1830 float2 per buffer
#define NTHREADS 224           // 7 warps: 14 items/tile = exactly 2 per warp
#define NTILES 8192            // 32 batch * 128 pairs * 2 halves
#define GRID 608               // 4 blocks/SM * 152 SMs

typedef unsigned long long ull;

__device__ __forceinline__ ull fma2(ull a, ull b, ull c) {
    ull d; asm("fma.rn.f32x2 %0, %1, %2, %3;" : "=l"(d) : "l"(a), "l"(b), "l"(c)); return d;
}
__device__ __forceinline__ ull pack2(float lo, float hi) {
    ull r; asm("mov.b64 %0, {%1, %2};" : "=l"(r) : "f"(lo), "f"(hi)); return r;
}
__device__ __forceinline__ float2 unpack2(ull v) {
    float2 r; asm("mov.b64 {%0, %1}, %2;" : "=f"(r.x), "=f"(r.y) : "l"(v)); return r;
}

__global__ __launch_bounds__(NTHREADS, 4)
void conv_butterfly_kernel(const float* __restrict__ x,
                           const float* __restrict__ w,
                           float* __restrict__ out)
{
    extern __shared__ float2 sm[];               // [2 buffers][SPLANE2]
    __shared__ __align__(16) ull wsm[18];        // per-dr groups: Wc0,Wc1,Wc2,Wp0,Wp1,Wp2

    const int tid    = threadIdx.x;
    const int warpid = tid >> 5;                 // 0..6
    const int lane   = tid & 31;
    const int lr     = lane & 3;
    const int lc     = lane >> 2;
    const uint32_t smem0 = (uint32_t)__cvta_generic_to_shared(sm);

    // ---- zero pad columns (0 = left halo, 57..60 incl. right halo 57) once; never rewritten
    for (int i = tid; i < 2 * TROWS * 5; i += NTHREADS) {
        const int rs = i / 5;                    // buffer*TROWS + row slot
        const int pc = i % 5;
        const int col = (pc == 0) ? 0 : (56 + pc);
        sm[rs * ST2 + col] = make_float2(0.f, 0.f);
    }

    // ---- prefetch half-tile t into buffer b (3360 4B copies, zfill OOB rows)
    auto prefetch = [&](int t, int b) {
        const int half = t & 1;
        const int p    = (t >> 1) & 127;
        const int n    = t >> 8;
        const int c    = ((p >> 2) << 3) + (p & 3);
        const int h0   = half * 28;
        const float* base = x + ((size_t)n * CH + c) * PLANE;
        #pragma unroll
        for (int k = 0; k < 15; k++) {
            const int i    = tid + k * NTHREADS;         // 0..3359
            const int slot = i / 112;                    // 0..29
            const int rem  = i - slot * 112;
            const int ch   = rem & 1;
            const int col  = rem >> 1;                   // 0..55
            const int h    = h0 - 1 + slot;              // -1..56
            const int sz   = (h >= 0 && h < HW) ? 4 : 0;
            const int hc   = min(max(h, 0), HW - 1);
            const float* src = base + ch * (4 * PLANE) + hc * HW + col;
            const uint32_t dst = smem0 +
                (uint32_t)(((b * SPLANE2 + slot * ST2 + 1 + col) << 3) + (ch << 2));
            asm volatile("cp.async.ca.shared.global [%0], [%1], 4, %2;"
                         :: "r"(dst), "l"(src), "r"(sz));
        }
    };

    int t = blockIdx.x;
    int b = 0;
    if (t < NTILES) prefetch(t, 0);
    asm volatile("cp.async.commit_group;");

    while (t < NTILES) {
        const int tn = t + GRID;
        if (tn < NTILES) prefetch(tn, b ^ 1);
        asm volatile("cp.async.commit_group;");

        const int half = t & 1;
        const int p    = (t >> 1) & 127;
        const int n    = t >> 8;
        const int c    = ((p >> 2) << 3) + (p & 3);
        const int h0   = half * 28;

        // stage packed weights in shared (18 threads, one ull each)
        if (tid < 18) {
            const float* wa = w + 18 * c;         // [w2c | w2c+1]
            const float* wb = w + 18 * (c + 4);   // [w2cp | w2cp+1]
            const int dr = tid / 6, sl = tid % 6;
            ull v;
            if (sl < 3) { const int k = dr * 3 + sl;     v = pack2(__ldg(wa + k),     __ldg(wb + 9 + k)); }
            else        { const int k = dr * 3 + sl - 3; v = pack2(__ldg(wa + 9 + k), __ldg(wb + k)); }
            wsm[tid] = v;
        }

        asm volatile("cp.async.wait_group 1;");
        __syncthreads();

        const ull* sbase = (const ull*)sm + b * SPLANE2;
        float* o0 = out + ((size_t)n * CH + c) * PLANE + h0 * HW;
        float* o1 = o0 + 4 * PLANE;

        const int rl = (warpid << 2) + lr;        // local output row 0..27

        #pragma unroll
        for (int pp = 0; pp < 2; pp++) {
            const int strip = (pp << 3) + lc;     // 0..15, active < 14
            if (strip < 14) {
                const int c0 = strip << 2;
                ull a0 = 0, a1 = 0, a2 = 0, a3 = 0;   // -> out[c]
                ull q0 = 0, q1 = 0, q2 = 0, q3 = 0;   // -> out[cp]
                #pragma unroll
                for (int dr = 0; dr < 3; dr++) {
                    const ull* qp = sbase + (rl + dr) * ST2 + c0;  // elements c0..c0+5
                    const ull v0 = qp[0], v1 = qp[1], v2 = qp[2];
                    const ull v3 = qp[3], v4 = qp[4], v5 = qp[5];
                    const ulonglong2 wA = *(const ulonglong2*)(wsm + dr * 6);
                    const ulonglong2 wB = *(const ulonglong2*)(wsm + dr * 6 + 2);
                    const ulonglong2 wC = *(const ulonglong2*)(wsm + dr * 6 + 4);
                    const ull wc0 = wA.x, wc1 = wA.y, wc2 = wB.x;
                    const ull wp0 = wB.y, wp1 = wC.x, wp2 = wC.y;

                    a0 = fma2(v0, wc0, a0); a0 = fma2(v1, wc1, a0); a0 = fma2(v2, wc2, a0);
                    a1 = fma2(v1, wc0, a1); a1 = fma2(v2, wc1, a1); a1 = fma2(v3, wc2, a1);
                    a2 = fma2(v2, wc0, a2); a2 = fma2(v3, wc1, a2); a2 = fma2(v4, wc2, a2);
                    a3 = fma2(v3, wc0, a3); a3 = fma2(v4, wc1, a3); a3 = fma2(v5, wc2, a3);

                    q0 = fma2(v0, wp0, q0); q0 = fma2(v1, wp1, q0); q0 = fma2(v2, wp2, q0);
                    q1 = fma2(v1, wp0, q1); q1 = fma2(v2, wp1, q1); q1 = fma2(v3, wp2, q1);
                    q2 = fma2(v2, wp0, q2); q2 = fma2(v3, wp1, q2); q2 = fma2(v4, wp2, q2);
                    q3 = fma2(v3, wp0, q3); q3 = fma2(v4, wp1, q3); q3 = fma2(v5, wp2, q3);
                }
                float2 u;
                float4 lo, hi;
                u = unpack2(a0); lo.x = u.x + u.y;
                u = unpack2(a1); lo.y = u.x + u.y;
                u = unpack2(a2); lo.z = u.x + u.y;
                u = unpack2(a3); lo.w = u.x + u.y;
                u = unpack2(q0); hi.x = u.x + u.y;
                u = unpack2(q1); hi.y = u.x + u.y;
                u = unpack2(q2); hi.z = u.x + u.y;
                u = unpack2(q3); hi.w = u.x + u.y;
                *(float4*)(o0 + rl * HW + c0) = lo;
                *(float4*)(o1 + rl * HW + c0) = hi;
            }
        }
        __syncthreads();      // protect buffer b and wsm before refill
        t = tn;
        b ^= 1;
    }
}

extern "C" void kernel_launch(void* const* d_in, const int* in_sizes, int n_in,
                              void* d_out, int out_size)
{
    const float* x = (const float*)d_in[0];
    const float* w = (const float*)d_in[1];
    float* out = (float*)d_out;
    (void)in_sizes; (void)n_in; (void)out_size;

    const int smem_bytes = 2 * SPLANE2 * (int)sizeof(float2);   // 29,280 B
    conv_butterfly_kernel<<<GRID, NTHREADS, smem_bytes>>>(x, w, out);
}